// round 7
// baseline (speedup 1.0000x reference)
#include <cuda_runtime.h>
#include <cstdint>

// Problem constants
#define BATCH 2048
#define SEQ   64
#define HEADS 8
#define M_ROWS (BATCH * SEQ)                  // 131072
#define OUT_ELEMS ((long long)M_ROWS * 512)   // 67108864

// Scratch (allocation-free rule: __device__ globals)
__device__ __align__(16) float g_q[(size_t)M_ROWS * 512];
__device__ __align__(16) float g_k[(size_t)M_ROWS * 512];
__device__ __align__(16) float g_v[(size_t)M_ROWS * 512];
__device__ __align__(16) float g_att[(size_t)M_ROWS * 512];

// ---------------------------------------------------------------------------
// TF32 helpers (legacy mma.sync path — compiles on plain sm_103 target)
// ---------------------------------------------------------------------------
__device__ __forceinline__ unsigned f2tf32(float f) {
    unsigned r;
    asm("cvt.rna.tf32.f32 %0, %1;" : "=r"(r) : "f"(f));
    return r;
}

__device__ __forceinline__ void mma_tf32(float c[4], const unsigned a[4],
                                         unsigned b0, unsigned b1) {
    asm volatile(
        "mma.sync.aligned.m16n8k8.row.col.f32.tf32.tf32.f32 "
        "{%0,%1,%2,%3}, {%4,%5,%6,%7}, {%8,%9}, {%0,%1,%2,%3};\n"
        : "+f"(c[0]), "+f"(c[1]), "+f"(c[2]), "+f"(c[3])
        : "r"(a[0]), "r"(a[1]), "r"(a[2]), "r"(a[3]), "r"(b0), "r"(b1));
}

// ---------------------------------------------------------------------------
// GEMM: C[M,512-chunk] = A[M,512] * W[512,512] + bias   (TF32 mma.sync)
// Block tile 128x256xK32, 256 threads = 8 warps (2x4), warp tile 64x64.
// Double-buffered smem stages, ONE __syncthreads per k-step.
// mode 0: A = X; blockIdx.x in [0,6): mat = bx>>1 (q/k/v), n0 = (bx&1)*256
// mode 1: A = g_att, W = Wo, C = Cout; blockIdx.x in [0,2)
// ---------------------------------------------------------------------------
#define APITCH 36            // (row*36 + k) banks: gid*4+tig -> all 32 distinct
#define BPITCH 264           // 264 mod 32 = 8 -> tig groups 8 banks apart
#define A_WORDS (128 * APITCH)      // 4608
#define B_WORDS (32 * BPITCH)       // 8448
#define GEMM_SMEM_BYTES ((2 * A_WORDS + 2 * B_WORDS) * 4)   // 104448

__global__ __launch_bounds__(256, 1)
void gemm_tf32(const float* __restrict__ X, float* __restrict__ Cout,
               const float* __restrict__ W0, const float* __restrict__ W1,
               const float* __restrict__ W2,
               const float* __restrict__ bias0, const float* __restrict__ bias1,
               const float* __restrict__ bias2, int mode)
{
    extern __shared__ unsigned smemw[];
    unsigned* const Abuf[2] = { smemw, smemw + A_WORDS };
    unsigned* const Bbuf[2] = { smemw + 2 * A_WORDS, smemw + 2 * A_WORDS + B_WORDS };

    const int t  = threadIdx.x;
    const int m0 = blockIdx.y * 128;

    const float* A; const float* W; const float* bias; float* C; int n0;
    if (mode == 0) {
        const int mat = blockIdx.x >> 1;
        n0 = (blockIdx.x & 1) * 256;
        A = X;
        W    = (mat == 0) ? W0 : (mat == 1) ? W1 : W2;
        bias = (mat == 0) ? bias0 : (mat == 1) ? bias1 : bias2;
        C    = (mat == 0) ? g_q : (mat == 1) ? g_k : g_v;
    } else {
        n0 = blockIdx.x * 256;
        A = g_att; W = W0; bias = bias0; C = Cout;
    }

    // staging maps (coalesced float4 LDG)
    const int af4  = t & 7;          // A float4-col 0..7  (k dim)
    const int arow = t >> 3;         // A row 0..31 (+32*i)
    const int bf4  = t & 63;         // B float4-col 0..63 (n dim)
    const int brow = t >> 6;         // B row 0..3 (+4*i)  (k dim)

    const float* Ap = A + (size_t)(m0 + arow) * 512 + af4 * 4;
    const float* Bp = W + (size_t)brow * 512 + n0 + bf4 * 4;

    // warp mapping: 2 (m) x 4 (n), warp tile 64x64
    const int w = t >> 5, lane = t & 31;
    const int gid = lane >> 2, tig = lane & 3;
    const int wm = (w & 1) * 64;
    const int wn = (w >> 1) * 64;

    float acc[4][8][4];
#pragma unroll
    for (int mi = 0; mi < 4; mi++)
#pragma unroll
        for (int nj = 0; nj < 8; nj++)
#pragma unroll
            for (int c = 0; c < 4; c++) acc[mi][nj][c] = 0.0f;

    float4 ra[4], rb[8];
    // prologue: kt = 0 load + stage into buf 0
#pragma unroll
    for (int i = 0; i < 4; i++) ra[i] = *(const float4*)(Ap + (size_t)(32 * i) * 512);
#pragma unroll
    for (int i = 0; i < 8; i++) rb[i] = *(const float4*)(Bp + (size_t)(4 * i) * 512);
#pragma unroll
    for (int i = 0; i < 4; i++) {
        uint4 u = make_uint4(f2tf32(ra[i].x), f2tf32(ra[i].y), f2tf32(ra[i].z), f2tf32(ra[i].w));
        *(uint4*)&Abuf[0][(arow + 32 * i) * APITCH + af4 * 4] = u;
    }
#pragma unroll
    for (int i = 0; i < 8; i++) {
        uint4 u = make_uint4(f2tf32(rb[i].x), f2tf32(rb[i].y), f2tf32(rb[i].z), f2tf32(rb[i].w));
        *(uint4*)&Bbuf[0][(brow + 4 * i) * BPITCH + bf4 * 4] = u;
    }
    __syncthreads();

    for (int kt = 0; kt < 16; kt++) {
        const int cb = kt & 1;
        // prefetch kt+1 (LDG in flight through the MMA phase)
        if (kt < 15) {
            const float* Ap2 = Ap + (kt + 1) * 32;
            const float* Bp2 = Bp + (size_t)((kt + 1) * 32) * 512;
#pragma unroll
            for (int i = 0; i < 4; i++) ra[i] = *(const float4*)(Ap2 + (size_t)(32 * i) * 512);
#pragma unroll
            for (int i = 0; i < 8; i++) rb[i] = *(const float4*)(Bp2 + (size_t)(4 * i) * 512);
        }

        const unsigned* as = Abuf[cb];
        const unsigned* bs = Bbuf[cb];
#pragma unroll
        for (int ks = 0; ks < 4; ks++) {
            const int k0 = ks * 8;
            unsigned a[4][4];
#pragma unroll
            for (int mi = 0; mi < 4; mi++) {
                const int r = wm + mi * 16 + gid;
                a[mi][0] = as[r * APITCH + k0 + tig];
                a[mi][1] = as[(r + 8) * APITCH + k0 + tig];
                a[mi][2] = as[r * APITCH + k0 + 4 + tig];
                a[mi][3] = as[(r + 8) * APITCH + k0 + 4 + tig];
            }
#pragma unroll
            for (int nj = 0; nj < 8; nj++) {
                const int c = wn + nj * 8 + gid;
                const unsigned b0 = bs[(k0 + tig) * BPITCH + c];
                const unsigned b1 = bs[(k0 + 4 + tig) * BPITCH + c];
#pragma unroll
                for (int mi = 0; mi < 4; mi++) mma_tf32(acc[mi][nj], a[mi], b0, b1);
            }
        }

        // stage kt+1 into the other buffer (its readers finished last iter)
        if (kt < 15) {
            const int nb = cb ^ 1;
#pragma unroll
            for (int i = 0; i < 4; i++) {
                uint4 u = make_uint4(f2tf32(ra[i].x), f2tf32(ra[i].y), f2tf32(ra[i].z), f2tf32(ra[i].w));
                *(uint4*)&Abuf[nb][(arow + 32 * i) * APITCH + af4 * 4] = u;
            }
#pragma unroll
            for (int i = 0; i < 8; i++) {
                uint4 u = make_uint4(f2tf32(rb[i].x), f2tf32(rb[i].y), f2tf32(rb[i].z), f2tf32(rb[i].w));
                *(uint4*)&Bbuf[nb][(brow + 4 * i) * BPITCH + bf4 * 4] = u;
            }
        }
        __syncthreads();
    }

    // epilogue: bias + float2 stores (4-lane 32B full sectors)
#pragma unroll
    for (int mi = 0; mi < 4; mi++) {
#pragma unroll
        for (int nj = 0; nj < 8; nj++) {
            const int row = m0 + wm + mi * 16 + gid;
            const int col = n0 + wn + nj * 8 + tig * 2;
            const float2 bv = *(const float2*)(bias + col);
            *(float2*)(C + (size_t)row * 512 + col) =
                make_float2(acc[mi][nj][0] + bv.x, acc[mi][nj][1] + bv.y);
            *(float2*)(C + (size_t)(row + 8) * 512 + col) =
                make_float2(acc[mi][nj][2] + bv.x, acc[mi][nj][3] + bv.y);
        }
    }
}

// ---------------------------------------------------------------------------
// Attention (unchanged, verified): one block per (b,h), fp32 SIMT
// ---------------------------------------------------------------------------
__global__ __launch_bounds__(256)
void attn_kernel(const float* __restrict__ mask)
{
    __shared__ float sA[64][68];
    __shared__ float sB[64][68];

    const int b = blockIdx.y;
    const int h = blockIdx.x;
    const int t = threadIdx.x;
    const size_t base = ((size_t)b * 64) * 512 + (size_t)h * 64;

#pragma unroll
    for (int i = 0; i < 4; i++) {
        const int idx = t + 256 * i;
        const int row = idx >> 4;
        const int c4  = (idx & 15) * 4;
        float4 qv = *(const float4*)(g_q + base + (size_t)row * 512 + c4);
        *(float4*)&sA[row][c4] = qv;
        float4 kv = *(const float4*)(g_k + base + (size_t)row * 512 + c4);
        sB[c4 + 0][row] = kv.x; sB[c4 + 1][row] = kv.y;
        sB[c4 + 2][row] = kv.z; sB[c4 + 3][row] = kv.w;
    }
    __syncthreads();

    const int ty = t >> 4, tx = t & 15;
    const int i0 = ty * 4, j0 = tx * 4;

    float acc[4][4];
#pragma unroll
    for (int r = 0; r < 4; r++)
#pragma unroll
        for (int c = 0; c < 4; c++) acc[r][c] = 0.0f;

#pragma unroll
    for (int d = 0; d < 64; d += 4) {
        float kc[4][4];
#pragma unroll
        for (int dd = 0; dd < 4; dd++) {
            float4 kv = *(const float4*)&sB[d + dd][j0];
            kc[dd][0] = kv.x; kc[dd][1] = kv.y; kc[dd][2] = kv.z; kc[dd][3] = kv.w;
        }
#pragma unroll
        for (int r = 0; r < 4; r++) {
            float4 qv = *(const float4*)&sA[i0 + r][d];
#pragma unroll
            for (int c = 0; c < 4; c++)
                acc[r][c] += qv.x * kc[0][c] + qv.y * kc[1][c] +
                             qv.z * kc[2][c] + qv.w * kc[3][c];
        }
    }

    const float* mrow = mask + ((size_t)b * 64) * 64;
    float p[4][4];
#pragma unroll
    for (int r = 0; r < 4; r++) {
        float4 mv = *(const float4*)(mrow + (size_t)(i0 + r) * 64 + j0);
        float s0 = acc[r][0] * 0.125f + __logf(mv.x + 1e-9f);
        float s1 = acc[r][1] * 0.125f + __logf(mv.y + 1e-9f);
        float s2 = acc[r][2] * 0.125f + __logf(mv.z + 1e-9f);
        float s3 = acc[r][3] * 0.125f + __logf(mv.w + 1e-9f);
        float mx = fmaxf(fmaxf(s0, s1), fmaxf(s2, s3));
        mx = fmaxf(mx, __shfl_xor_sync(0xffffffffu, mx, 1));
        mx = fmaxf(mx, __shfl_xor_sync(0xffffffffu, mx, 2));
        mx = fmaxf(mx, __shfl_xor_sync(0xffffffffu, mx, 4));
        mx = fmaxf(mx, __shfl_xor_sync(0xffffffffu, mx, 8));
        float e0 = __expf(s0 - mx), e1 = __expf(s1 - mx);
        float e2 = __expf(s2 - mx), e3 = __expf(s3 - mx);
        float sum = e0 + e1 + e2 + e3;
        sum += __shfl_xor_sync(0xffffffffu, sum, 1);
        sum += __shfl_xor_sync(0xffffffffu, sum, 2);
        sum += __shfl_xor_sync(0xffffffffu, sum, 4);
        sum += __shfl_xor_sync(0xffffffffu, sum, 8);
        const float inv = 1.0f / sum;
        p[r][0] = e0 * inv; p[r][1] = e1 * inv; p[r][2] = e2 * inv; p[r][3] = e3 * inv;
    }

    __syncthreads();

#pragma unroll
    for (int r = 0; r < 4; r++)
        *(float4*)&sA[i0 + r][j0] = make_float4(p[r][0], p[r][1], p[r][2], p[r][3]);
#pragma unroll
    for (int i = 0; i < 4; i++) {
        const int idx = t + 256 * i;
        const int row = idx >> 4;
        const int c4  = (idx & 15) * 4;
        *(float4*)&sB[row][c4] = *(const float4*)(g_v + base + (size_t)row * 512 + c4);
    }
    __syncthreads();

    float o[4][4];
#pragma unroll
    for (int r = 0; r < 4; r++)
#pragma unroll
        for (int c = 0; c < 4; c++) o[r][c] = 0.0f;

#pragma unroll
    for (int j = 0; j < 64; j += 4) {
        float vc[4][4];
#pragma unroll
        for (int jj = 0; jj < 4; jj++) {
            float4 vv = *(const float4*)&sB[j + jj][j0];
            vc[jj][0] = vv.x; vc[jj][1] = vv.y; vc[jj][2] = vv.z; vc[jj][3] = vv.w;
        }
#pragma unroll
        for (int r = 0; r < 4; r++) {
            float4 pv = *(const float4*)&sA[i0 + r][j];
#pragma unroll
            for (int c = 0; c < 4; c++)
                o[r][c] += pv.x * vc[0][c] + pv.y * vc[1][c] +
                           pv.z * vc[2][c] + pv.w * vc[3][c];
        }
    }

#pragma unroll
    for (int r = 0; r < 4; r++)
        *(float4*)(g_att + base + (size_t)(i0 + r) * 512 + j0) =
            make_float4(o[r][0], o[r][1], o[r][2], o[r][3]);
}

__global__ void tail_zero(float* __restrict__ out, long long start, long long total)
{
    long long i = start + (long long)blockIdx.x * blockDim.x + threadIdx.x;
    if (i < total) out[i] = 0.0f;
}

// ---------------------------------------------------------------------------
extern "C" void kernel_launch(void* const* d_in, const int* in_sizes, int n_in,
                              void* d_out, int out_size)
{
    const float* x    = (const float*)d_in[0];
    const float* mask = (const float*)d_in[1];
    const float* Wq   = (const float*)d_in[2];
    const float* bq   = (const float*)d_in[3];
    const float* Wk   = (const float*)d_in[4];
    const float* bk   = (const float*)d_in[5];
    const float* Wv   = (const float*)d_in[6];
    const float* bv   = (const float*)d_in[7];
    const float* Wo   = (const float*)d_in[8];
    const float* bo   = (const float*)d_in[9];
    float* out = (float*)d_out;

    cudaFuncSetAttribute(gemm_tf32,
                         cudaFuncAttributeMaxDynamicSharedMemorySize, GEMM_SMEM_BYTES);

    // 0) Tail first (disjoint from main output; puts the QKV GEMM at ncu's
    //    fixed skip-5 capture slot on the next profiling pass)
    long long tail = (long long)out_size - OUT_ELEMS;
    if (tail > 0) {
        int blocks = (int)((tail + 255) / 256);
        tail_zero<<<blocks, 256>>>(out, OUT_ELEMS, (long long)out_size);
    }

    // 1) Fused QKV projections (grid.x = 6 -> {q,k,v} x 2 n-tiles of 256)
    gemm_tf32<<<dim3(6, 1024), 256, GEMM_SMEM_BYTES>>>(
        x, nullptr, Wq, Wk, Wv, bq, bk, bv, 0);

    // 2) Channel-masked attention
    attn_kernel<<<dim3(HEADS, BATCH), 256>>>(mask);

    // 3) Output projection (grid.x = 2)
    gemm_tf32<<<dim3(2, 1024), 256, GEMM_SMEM_BYTES>>>(
        nullptr, out, Wo, Wo, Wo, bo, bo, bo, 1);
}

// round 8
// speedup vs baseline: 1.1197x; 1.1197x over previous
#include <cuda_runtime.h>
#include <cstdint>

// Problem constants
#define BATCH 2048
#define SEQ   64
#define HEADS 8
#define M_ROWS (BATCH * SEQ)                  // 131072
#define OUT_ELEMS ((long long)M_ROWS * 512)   // 67108864

// Scratch (allocation-free rule: __device__ globals)
__device__ __align__(16) float g_q[(size_t)M_ROWS * 512];
__device__ __align__(16) float g_k[(size_t)M_ROWS * 512];
__device__ __align__(16) float g_v[(size_t)M_ROWS * 512];
__device__ __align__(16) float g_att[(size_t)M_ROWS * 512];

// ---------------------------------------------------------------------------
// fp16 helpers
// ---------------------------------------------------------------------------
__device__ __forceinline__ uint32_t pack_h2(float lo, float hi) {
    // d.lo = second PTX source, d.hi = first
    uint32_t r;
    asm("cvt.rn.f16x2.f32 %0, %1, %2;" : "=r"(r) : "f"(hi), "f"(lo));
    return r;
}

__device__ __forceinline__ void mma_f16(float c[4], const uint32_t a[4],
                                        uint32_t b0, uint32_t b1) {
    asm volatile(
        "mma.sync.aligned.m16n8k16.row.col.f32.f16.f16.f32 "
        "{%0,%1,%2,%3}, {%4,%5,%6,%7}, {%8,%9}, {%0,%1,%2,%3};\n"
        : "+f"(c[0]), "+f"(c[1]), "+f"(c[2]), "+f"(c[3])
        : "r"(a[0]), "r"(a[1]), "r"(a[2]), "r"(a[3]), "r"(b0), "r"(b1));
}

// ---------------------------------------------------------------------------
// GEMM: C[M,512] = A[M,512] * W[512,512] + bias   (fp16 mma.sync, fp32 accum)
// Block tile 128x128xK32, 256 threads = 8 warps (4m x 2n), warp tile 32x64.
// Operands packed as f16x2 words in smem:
//   As[row][kk]  kk = k/2, pitch 20  -> frag reads hit all 32 banks
//   Bs[kk][n]    pairs (k even, k odd), pitch 136 -> all 32 banks
// Double-buffered, ONE __syncthreads per k-step.
// mode 0: A = X; blockIdx.x: mat = bx>>2 (q/k/v), n0 = (bx&3)*128
// mode 1: A = g_att, W = W0, C = Cout
// ---------------------------------------------------------------------------
#define APITCH 20
#define BPITCH 136
#define A_WORDS (128 * APITCH)   // 2560
#define B_WORDS (16 * BPITCH)    // 2176

__global__ __launch_bounds__(256, 2)
void gemm_f16(const float* __restrict__ X, float* __restrict__ Cout,
              const float* __restrict__ W0, const float* __restrict__ W1,
              const float* __restrict__ W2,
              const float* __restrict__ bias0, const float* __restrict__ bias1,
              const float* __restrict__ bias2, int mode)
{
    __shared__ uint32_t Asm[2][A_WORDS];
    __shared__ uint32_t Bsm[2][B_WORDS];

    const int t  = threadIdx.x;
    const int m0 = blockIdx.y * 128;

    const float* A; const float* W; const float* bias; float* C; int n0;
    if (mode == 0) {
        const int mat = blockIdx.x >> 2;
        n0 = (blockIdx.x & 3) * 128;
        A = X;
        W    = (mat == 0) ? W0 : (mat == 1) ? W1 : W2;
        bias = (mat == 0) ? bias0 : (mat == 1) ? bias1 : bias2;
        C    = (mat == 0) ? g_q : (mat == 1) ? g_k : g_v;
    } else {
        n0 = blockIdx.x * 128;
        A = g_att; W = W0; bias = bias0; C = Cout;
    }

    // staging maps
    const int arow = t >> 1;           // 0..127
    const int ah   = t & 1;            // halves of the 32-float k chunk
    const int kkr  = t >> 4;           // 0..15 (packed-k row of B)
    const int nc   = (t & 15) * 8;     // n col 0..120

    const float* Ap  = A + (size_t)(m0 + arow) * 512 + ah * 16;
    const float* Bp0 = W + (size_t)(2 * kkr)     * 512 + n0 + nc;
    const float* Bp1 = W + (size_t)(2 * kkr + 1) * 512 + n0 + nc;

    // warp mapping: 4 (m) x 2 (n), warp tile 32x64
    const int w = t >> 5, lane = t & 31;
    const int gid = lane >> 2, tig = lane & 3;
    const int wm = (w & 3) * 32;
    const int wn = (w >> 2) * 64;

    float acc[2][8][4];
#pragma unroll
    for (int mi = 0; mi < 2; mi++)
#pragma unroll
        for (int nj = 0; nj < 8; nj++)
#pragma unroll
            for (int c = 0; c < 4; c++) acc[mi][nj][c] = 0.0f;

    float4 ra[4], rb[4];
    // prologue: load kt=0 and stage into buf 0
#pragma unroll
    for (int j = 0; j < 4; j++) ra[j] = *(const float4*)(Ap + j * 4);
#pragma unroll
    for (int j = 0; j < 2; j++) {
        rb[j]     = *(const float4*)(Bp0 + j * 4);
        rb[2 + j] = *(const float4*)(Bp1 + j * 4);
    }
    {
#pragma unroll
        for (int j = 0; j < 2; j++) {
            uint4 u = make_uint4(pack_h2(ra[2*j].x, ra[2*j].y), pack_h2(ra[2*j].z, ra[2*j].w),
                                 pack_h2(ra[2*j+1].x, ra[2*j+1].y), pack_h2(ra[2*j+1].z, ra[2*j+1].w));
            *(uint4*)&Asm[0][arow * APITCH + ah * 8 + 4 * j] = u;
        }
#pragma unroll
        for (int j = 0; j < 2; j++) {
            const float* lo = (const float*)&rb[j];
            const float* hi = (const float*)&rb[2 + j];
            uint4 u = make_uint4(pack_h2(lo[0], hi[0]), pack_h2(lo[1], hi[1]),
                                 pack_h2(lo[2], hi[2]), pack_h2(lo[3], hi[3]));
            *(uint4*)&Bsm[0][kkr * BPITCH + nc + 4 * j] = u;
        }
    }
    __syncthreads();

    for (int kt = 0; kt < 16; kt++) {
        const int cb = kt & 1;
        // prefetch kt+1 (LDG in flight through the MMA phase)
        if (kt < 15) {
            const float* Ap2  = Ap + (kt + 1) * 32;
            const float* Bp02 = Bp0 + (size_t)((kt + 1) * 32) * 512;
            const float* Bp12 = Bp1 + (size_t)((kt + 1) * 32) * 512;
#pragma unroll
            for (int j = 0; j < 4; j++) ra[j] = *(const float4*)(Ap2 + j * 4);
#pragma unroll
            for (int j = 0; j < 2; j++) {
                rb[j]     = *(const float4*)(Bp02 + j * 4);
                rb[2 + j] = *(const float4*)(Bp12 + j * 4);
            }
        }

        const uint32_t* as = Asm[cb];
        const uint32_t* bs = Bsm[cb];
#pragma unroll
        for (int ks = 0; ks < 2; ks++) {
            const int kb = ks * 8;
            uint32_t a[2][4];
#pragma unroll
            for (int mi = 0; mi < 2; mi++) {
                const int r = wm + mi * 16 + gid;
                a[mi][0] = as[r * APITCH + kb + tig];
                a[mi][1] = as[(r + 8) * APITCH + kb + tig];
                a[mi][2] = as[r * APITCH + kb + 4 + tig];
                a[mi][3] = as[(r + 8) * APITCH + kb + 4 + tig];
            }
#pragma unroll
            for (int nj = 0; nj < 8; nj++) {
                const int c = wn + nj * 8 + gid;
                const uint32_t b0 = bs[(kb + tig) * BPITCH + c];
                const uint32_t b1 = bs[(kb + 4 + tig) * BPITCH + c];
                mma_f16(acc[0][nj], a[0], b0, b1);
                mma_f16(acc[1][nj], a[1], b0, b1);
            }
        }

        // stage kt+1 into the other buffer (its readers finished last iter)
        if (kt < 15) {
            const int nb = cb ^ 1;
#pragma unroll
            for (int j = 0; j < 2; j++) {
                uint4 u = make_uint4(pack_h2(ra[2*j].x, ra[2*j].y), pack_h2(ra[2*j].z, ra[2*j].w),
                                     pack_h2(ra[2*j+1].x, ra[2*j+1].y), pack_h2(ra[2*j+1].z, ra[2*j+1].w));
                *(uint4*)&Asm[nb][arow * APITCH + ah * 8 + 4 * j] = u;
            }
#pragma unroll
            for (int j = 0; j < 2; j++) {
                const float* lo = (const float*)&rb[j];
                const float* hi = (const float*)&rb[2 + j];
                uint4 u = make_uint4(pack_h2(lo[0], hi[0]), pack_h2(lo[1], hi[1]),
                                     pack_h2(lo[2], hi[2]), pack_h2(lo[3], hi[3]));
                *(uint4*)&Bsm[nb][kkr * BPITCH + nc + 4 * j] = u;
            }
        }
        __syncthreads();
    }

    // epilogue: bias + float2 stores
#pragma unroll
    for (int mi = 0; mi < 2; mi++) {
#pragma unroll
        for (int nj = 0; nj < 8; nj++) {
            const int row = m0 + wm + mi * 16 + gid;
            const int col = n0 + wn + nj * 8 + tig * 2;
            const float2 bv = *(const float2*)(bias + col);
            *(float2*)(C + (size_t)row * 512 + col) =
                make_float2(acc[mi][nj][0] + bv.x, acc[mi][nj][1] + bv.y);
            *(float2*)(C + (size_t)(row + 8) * 512 + col) =
                make_float2(acc[mi][nj][2] + bv.x, acc[mi][nj][3] + bv.y);
        }
    }
}

// ---------------------------------------------------------------------------
// Attention (unchanged, verified): one block per (b,h), fp32 SIMT
// ---------------------------------------------------------------------------
__global__ __launch_bounds__(256)
void attn_kernel(const float* __restrict__ mask)
{
    __shared__ float sA[64][68];
    __shared__ float sB[64][68];

    const int b = blockIdx.y;
    const int h = blockIdx.x;
    const int t = threadIdx.x;
    const size_t base = ((size_t)b * 64) * 512 + (size_t)h * 64;

#pragma unroll
    for (int i = 0; i < 4; i++) {
        const int idx = t + 256 * i;
        const int row = idx >> 4;
        const int c4  = (idx & 15) * 4;
        float4 qv = *(const float4*)(g_q + base + (size_t)row * 512 + c4);
        *(float4*)&sA[row][c4] = qv;
        float4 kv = *(const float4*)(g_k + base + (size_t)row * 512 + c4);
        sB[c4 + 0][row] = kv.x; sB[c4 + 1][row] = kv.y;
        sB[c4 + 2][row] = kv.z; sB[c4 + 3][row] = kv.w;
    }
    __syncthreads();

    const int ty = t >> 4, tx = t & 15;
    const int i0 = ty * 4, j0 = tx * 4;

    float acc[4][4];
#pragma unroll
    for (int r = 0; r < 4; r++)
#pragma unroll
        for (int c = 0; c < 4; c++) acc[r][c] = 0.0f;

#pragma unroll
    for (int d = 0; d < 64; d += 4) {
        float kc[4][4];
#pragma unroll
        for (int dd = 0; dd < 4; dd++) {
            float4 kv = *(const float4*)&sB[d + dd][j0];
            kc[dd][0] = kv.x; kc[dd][1] = kv.y; kc[dd][2] = kv.z; kc[dd][3] = kv.w;
        }
#pragma unroll
        for (int r = 0; r < 4; r++) {
            float4 qv = *(const float4*)&sA[i0 + r][d];
#pragma unroll
            for (int c = 0; c < 4; c++)
                acc[r][c] += qv.x * kc[0][c] + qv.y * kc[1][c] +
                             qv.z * kc[2][c] + qv.w * kc[3][c];
        }
    }

    const float* mrow = mask + ((size_t)b * 64) * 64;
    float p[4][4];
#pragma unroll
    for (int r = 0; r < 4; r++) {
        float4 mv = *(const float4*)(mrow + (size_t)(i0 + r) * 64 + j0);
        float s0 = acc[r][0] * 0.125f + __logf(mv.x + 1e-9f);
        float s1 = acc[r][1] * 0.125f + __logf(mv.y + 1e-9f);
        float s2 = acc[r][2] * 0.125f + __logf(mv.z + 1e-9f);
        float s3 = acc[r][3] * 0.125f + __logf(mv.w + 1e-9f);
        float mx = fmaxf(fmaxf(s0, s1), fmaxf(s2, s3));
        mx = fmaxf(mx, __shfl_xor_sync(0xffffffffu, mx, 1));
        mx = fmaxf(mx, __shfl_xor_sync(0xffffffffu, mx, 2));
        mx = fmaxf(mx, __shfl_xor_sync(0xffffffffu, mx, 4));
        mx = fmaxf(mx, __shfl_xor_sync(0xffffffffu, mx, 8));
        float e0 = __expf(s0 - mx), e1 = __expf(s1 - mx);
        float e2 = __expf(s2 - mx), e3 = __expf(s3 - mx);
        float sum = e0 + e1 + e2 + e3;
        sum += __shfl_xor_sync(0xffffffffu, sum, 1);
        sum += __shfl_xor_sync(0xffffffffu, sum, 2);
        sum += __shfl_xor_sync(0xffffffffu, sum, 4);
        sum += __shfl_xor_sync(0xffffffffu, sum, 8);
        const float inv = 1.0f / sum;
        p[r][0] = e0 * inv; p[r][1] = e1 * inv; p[r][2] = e2 * inv; p[r][3] = e3 * inv;
    }

    __syncthreads();

#pragma unroll
    for (int r = 0; r < 4; r++)
        *(float4*)&sA[i0 + r][j0] = make_float4(p[r][0], p[r][1], p[r][2], p[r][3]);
#pragma unroll
    for (int i = 0; i < 4; i++) {
        const int idx = t + 256 * i;
        const int row = idx >> 4;
        const int c4  = (idx & 15) * 4;
        *(float4*)&sB[row][c4] = *(const float4*)(g_v + base + (size_t)row * 512 + c4);
    }
    __syncthreads();

    float o[4][4];
#pragma unroll
    for (int r = 0; r < 4; r++)
#pragma unroll
        for (int c = 0; c < 4; c++) o[r][c] = 0.0f;

#pragma unroll
    for (int j = 0; j < 64; j += 4) {
        float vc[4][4];
#pragma unroll
        for (int jj = 0; jj < 4; jj++) {
            float4 vv = *(const float4*)&sB[j + jj][j0];
            vc[jj][0] = vv.x; vc[jj][1] = vv.y; vc[jj][2] = vv.z; vc[jj][3] = vv.w;
        }
#pragma unroll
        for (int r = 0; r < 4; r++) {
            float4 pv = *(const float4*)&sA[i0 + r][j];
#pragma unroll
            for (int c = 0; c < 4; c++)
                o[r][c] += pv.x * vc[0][c] + pv.y * vc[1][c] +
                           pv.z * vc[2][c] + pv.w * vc[3][c];
        }
    }

#pragma unroll
    for (int r = 0; r < 4; r++)
        *(float4*)(g_att + base + (size_t)(i0 + r) * 512 + j0) =
            make_float4(o[r][0], o[r][1], o[r][2], o[r][3]);
}

__global__ void tail_zero(float* __restrict__ out, long long start, long long total)
{
    long long i = start + (long long)blockIdx.x * blockDim.x + threadIdx.x;
    if (i < total) out[i] = 0.0f;
}

// ---------------------------------------------------------------------------
extern "C" void kernel_launch(void* const* d_in, const int* in_sizes, int n_in,
                              void* d_out, int out_size)
{
    const float* x    = (const float*)d_in[0];
    const float* mask = (const float*)d_in[1];
    const float* Wq   = (const float*)d_in[2];
    const float* bq   = (const float*)d_in[3];
    const float* Wk   = (const float*)d_in[4];
    const float* bk   = (const float*)d_in[5];
    const float* Wv   = (const float*)d_in[6];
    const float* bv   = (const float*)d_in[7];
    const float* Wo   = (const float*)d_in[8];
    const float* bo   = (const float*)d_in[9];
    float* out = (float*)d_out;

    // 0) Tail first (ccd_loss scalar / padding)
    long long tail = (long long)out_size - OUT_ELEMS;
    if (tail > 0) {
        int blocks = (int)((tail + 255) / 256);
        tail_zero<<<blocks, 256>>>(out, OUT_ELEMS, (long long)out_size);
    }

    // 1) Fused QKV projections (grid.x = 12 -> {q,k,v} x 4 n-tiles of 128)
    gemm_f16<<<dim3(12, 1024), 256>>>(x, nullptr, Wq, Wk, Wv, bq, bk, bv, 0);

    // 2) Channel-masked attention
    attn_kernel<<<dim3(HEADS, BATCH), 256>>>(mask);

    // 3) Output projection (grid.x = 4)
    gemm_f16<<<dim3(4, 1024), 256>>>(nullptr, out, Wo, Wo, Wo, bo, bo, bo, 1);
}

// round 13
// speedup vs baseline: 1.1829x; 1.0564x over previous
#include <cuda_runtime.h>
#include <cstdint>

// Problem constants
#define BATCH 2048
#define SEQ   64
#define HEADS 8
#define M_ROWS (BATCH * SEQ)                  // 131072
#define OUT_ELEMS ((long long)M_ROWS * 512)   // 67108864

// Scratch (allocation-free rule: __device__ globals) — same four as R8 pass
__device__ __align__(16) float g_q[(size_t)M_ROWS * 512];
__device__ __align__(16) float g_k[(size_t)M_ROWS * 512];
__device__ __align__(16) float g_v[(size_t)M_ROWS * 512];
__device__ __align__(16) float g_att[(size_t)M_ROWS * 512];

// ---------------------------------------------------------------------------
// fp16 helpers
// ---------------------------------------------------------------------------
__device__ __forceinline__ uint32_t pack_h2(float lo, float hi) {
    // d.lo = second PTX source, d.hi = first
    uint32_t r;
    asm("cvt.rn.f16x2.f32 %0, %1, %2;" : "=r"(r) : "f"(hi), "f"(lo));
    return r;
}

__device__ __forceinline__ void mma_f16(float c[4], const uint32_t a[4],
                                        uint32_t b0, uint32_t b1) {
    asm volatile(
        "mma.sync.aligned.m16n8k16.row.col.f32.f16.f16.f32 "
        "{%0,%1,%2,%3}, {%4,%5,%6,%7}, {%8,%9}, {%0,%1,%2,%3};\n"
        : "+f"(c[0]), "+f"(c[1]), "+f"(c[2]), "+f"(c[3])
        : "r"(a[0]), "r"(a[1]), "r"(a[2]), "r"(a[3]), "r"(b0), "r"(b1));
}

// ---------------------------------------------------------------------------
// GEMM: C[M,512] = A[M,512] * W[512,512] + bias   (fp16 mma.sync, fp32 accum)
// Block tile 128x128xK32, 256 threads = 8 warps (4m x 2n), warp tile 32x64.
// R8-proven skeleton. Delta vs R8: A smem words PAIR-INTERLEAVED within each
// 8-word half (pos(q) = 2*(q&3) + (q>>2)), pitch 20 -> 24, so each A fragment
// read is one LDS.64 hitting all 32 banks per half-warp phase.
//   As[row][ah*8 + pos]  pitch 24 words
//   Bs[kk][n] pairs (k even, k odd), pitch 136 (unchanged, R8-proven)
// Double-buffered, ONE __syncthreads per k-step.
// mode 0: A = X; blockIdx.x: mat = bx>>2 (q/k/v), n0 = (bx&3)*128
// mode 1: A = g_att, W = W0, C = Cout
// ---------------------------------------------------------------------------
#define APITCH 24
#define BPITCH 136
#define A_WORDS (128 * APITCH)   // 3072
#define B_WORDS (16 * BPITCH)    // 2176

__global__ __launch_bounds__(256, 2)
void gemm_f16(const float* __restrict__ X, float* __restrict__ Cout,
              const float* __restrict__ W0, const float* __restrict__ W1,
              const float* __restrict__ W2,
              const float* __restrict__ bias0, const float* __restrict__ bias1,
              const float* __restrict__ bias2, int mode)
{
    __shared__ uint32_t Asm[2][A_WORDS];
    __shared__ uint32_t Bsm[2][B_WORDS];

    const int t  = threadIdx.x;
    const int m0 = blockIdx.y * 128;

    const float* A; const float* W; const float* bias; float* C; int n0;
    if (mode == 0) {
        const int mat = blockIdx.x >> 2;
        n0 = (blockIdx.x & 3) * 128;
        A = X;
        W    = (mat == 0) ? W0 : (mat == 1) ? W1 : W2;
        bias = (mat == 0) ? bias0 : (mat == 1) ? bias1 : bias2;
        C    = (mat == 0) ? g_q : (mat == 1) ? g_k : g_v;
    } else {
        n0 = blockIdx.x * 128;
        A = g_att; W = W0; bias = bias0; C = Cout;
    }

    // staging maps (identical to R8)
    const int arow = t >> 1;           // 0..127
    const int ah   = t & 1;            // halves of the 32-float k chunk
    const int kkr  = t >> 4;           // 0..15 (packed-k row of B)
    const int nc   = (t & 15) * 8;     // n col 0..120

    const float* Ap  = A + (size_t)(m0 + arow) * 512 + ah * 16;
    const float* Bp0 = W + (size_t)(2 * kkr)     * 512 + n0 + nc;
    const float* Bp1 = W + (size_t)(2 * kkr + 1) * 512 + n0 + nc;

    // warp mapping (identical to R8): 4 (m) x 2 (n), warp tile 32x64
    const int w = t >> 5, lane = t & 31;
    const int gid = lane >> 2, tig = lane & 3;
    const int wm = (w & 3) * 32;
    const int wn = (w >> 2) * 64;

    float acc[2][8][4];
#pragma unroll
    for (int mi = 0; mi < 2; mi++)
#pragma unroll
        for (int nj = 0; nj < 8; nj++)
#pragma unroll
            for (int c = 0; c < 4; c++) acc[mi][nj][c] = 0.0f;

    float4 ra[4], rb[4];
    // prologue: load kt=0 and stage into buf 0
#pragma unroll
    for (int j = 0; j < 4; j++) ra[j] = *(const float4*)(Ap + j * 4);
#pragma unroll
    for (int j = 0; j < 2; j++) {
        rb[j]     = *(const float4*)(Bp0 + j * 4);
        rb[2 + j] = *(const float4*)(Bp1 + j * 4);
    }
    {
        // A: words w[q] = pair q of this half; store interleaved
        // order (w0,w4,w1,w5) (w2,w6,w3,w7): pos(q) = 2*(q&3) + (q>>2)
        uint32_t wv[8];
#pragma unroll
        for (int j = 0; j < 4; j++) {
            wv[2 * j]     = pack_h2(ra[j].x, ra[j].y);
            wv[2 * j + 1] = pack_h2(ra[j].z, ra[j].w);
        }
        *(uint4*)&Asm[0][arow * APITCH + ah * 8]     = make_uint4(wv[0], wv[4], wv[1], wv[5]);
        *(uint4*)&Asm[0][arow * APITCH + ah * 8 + 4] = make_uint4(wv[2], wv[6], wv[3], wv[7]);
#pragma unroll
        for (int j = 0; j < 2; j++) {
            const float* lo = (const float*)&rb[j];
            const float* hi = (const float*)&rb[2 + j];
            uint4 u = make_uint4(pack_h2(lo[0], hi[0]), pack_h2(lo[1], hi[1]),
                                 pack_h2(lo[2], hi[2]), pack_h2(lo[3], hi[3]));
            *(uint4*)&Bsm[0][kkr * BPITCH + nc + 4 * j] = u;
        }
    }
    __syncthreads();

    for (int kt = 0; kt < 16; kt++) {
        const int cb = kt & 1;
        // prefetch kt+1 (LDG in flight through the MMA phase)
        if (kt < 15) {
            const float* Ap2  = Ap + (kt + 1) * 32;
            const float* Bp02 = Bp0 + (size_t)((kt + 1) * 32) * 512;
            const float* Bp12 = Bp1 + (size_t)((kt + 1) * 32) * 512;
#pragma unroll
            for (int j = 0; j < 4; j++) ra[j] = *(const float4*)(Ap2 + j * 4);
#pragma unroll
            for (int j = 0; j < 2; j++) {
                rb[j]     = *(const float4*)(Bp02 + j * 4);
                rb[2 + j] = *(const float4*)(Bp12 + j * 4);
            }
        }

        const uint32_t* as = Asm[cb];
        const uint32_t* bs = Bsm[cb];
#pragma unroll
        for (int ks = 0; ks < 2; ks++) {
            const int kb = ks * 8;
            const int kw = kb + tig * 2;      // interleaved: (pair kb+tig, pair kb+4+tig)
            uint32_t a[2][4];
#pragma unroll
            for (int mi = 0; mi < 2; mi++) {
                const int r = wm + mi * 16 + gid;
                const uint2 lo = *(const uint2*)(as + r * APITCH + kw);
                const uint2 hi = *(const uint2*)(as + (r + 8) * APITCH + kw);
                a[mi][0] = lo.x; a[mi][1] = hi.x; a[mi][2] = lo.y; a[mi][3] = hi.y;
            }
#pragma unroll
            for (int nj = 0; nj < 8; nj++) {
                const int c = wn + nj * 8 + gid;
                const uint32_t b0 = bs[(kb + tig) * BPITCH + c];
                const uint32_t b1 = bs[(kb + 4 + tig) * BPITCH + c];
                mma_f16(acc[0][nj], a[0], b0, b1);
                mma_f16(acc[1][nj], a[1], b0, b1);
            }
        }

        // stage kt+1 into the other buffer (its readers finished last iter)
        if (kt < 15) {
            const int nb = cb ^ 1;
            uint32_t wv[8];
#pragma unroll
            for (int j = 0; j < 4; j++) {
                wv[2 * j]     = pack_h2(ra[j].x, ra[j].y);
                wv[2 * j + 1] = pack_h2(ra[j].z, ra[j].w);
            }
            *(uint4*)&Asm[nb][arow * APITCH + ah * 8]     = make_uint4(wv[0], wv[4], wv[1], wv[5]);
            *(uint4*)&Asm[nb][arow * APITCH + ah * 8 + 4] = make_uint4(wv[2], wv[6], wv[3], wv[7]);
#pragma unroll
            for (int j = 0; j < 2; j++) {
                const float* lo = (const float*)&rb[j];
                const float* hi = (const float*)&rb[2 + j];
                uint4 u = make_uint4(pack_h2(lo[0], hi[0]), pack_h2(lo[1], hi[1]),
                                     pack_h2(lo[2], hi[2]), pack_h2(lo[3], hi[3]));
                *(uint4*)&Bsm[nb][kkr * BPITCH + nc + 4 * j] = u;
            }
        }
        __syncthreads();
    }

    // epilogue (R8-proven): bias + float2 stores
#pragma unroll
    for (int mi = 0; mi < 2; mi++) {
#pragma unroll
        for (int nj = 0; nj < 8; nj++) {
            const int row = m0 + wm + mi * 16 + gid;
            const int col = n0 + wn + nj * 8 + tig * 2;
            const float2 bv = *(const float2*)(bias + col);
            *(float2*)(C + (size_t)row * 512 + col) =
                make_float2(acc[mi][nj][0] + bv.x, acc[mi][nj][1] + bv.y);
            *(float2*)(C + (size_t)(row + 8) * 512 + col) =
                make_float2(acc[mi][nj][2] + bv.x, acc[mi][nj][3] + bv.y);
        }
    }
}

// ---------------------------------------------------------------------------
// Attention (byte-identical to R8 pass): one block per (b,h), fp32 SIMT
// ---------------------------------------------------------------------------
__global__ __launch_bounds__(256)
void attn_kernel(const float* __restrict__ mask)
{
    __shared__ float sA[64][68];
    __shared__ float sB[64][68];

    const int b = blockIdx.y;
    const int h = blockIdx.x;
    const int t = threadIdx.x;
    const size_t base = ((size_t)b * 64) * 512 + (size_t)h * 64;

#pragma unroll
    for (int i = 0; i < 4; i++) {
        const int idx = t + 256 * i;
        const int row = idx >> 4;
        const int c4  = (idx & 15) * 4;
        float4 qv = *(const float4*)(g_q + base + (size_t)row * 512 + c4);
        *(float4*)&sA[row][c4] = qv;
        float4 kv = *(const float4*)(g_k + base + (size_t)row * 512 + c4);
        sB[c4 + 0][row] = kv.x; sB[c4 + 1][row] = kv.y;
        sB[c4 + 2][row] = kv.z; sB[c4 + 3][row] = kv.w;
    }
    __syncthreads();

    const int ty = t >> 4, tx = t & 15;
    const int i0 = ty * 4, j0 = tx * 4;

    float acc[4][4];
#pragma unroll
    for (int r = 0; r < 4; r++)
#pragma unroll
        for (int c = 0; c < 4; c++) acc[r][c] = 0.0f;

#pragma unroll
    for (int d = 0; d < 64; d += 4) {
        float kc[4][4];
#pragma unroll
        for (int dd = 0; dd < 4; dd++) {
            float4 kv = *(const float4*)&sB[d + dd][j0];
            kc[dd][0] = kv.x; kc[dd][1] = kv.y; kc[dd][2] = kv.z; kc[dd][3] = kv.w;
        }
#pragma unroll
        for (int r = 0; r < 4; r++) {
            float4 qv = *(const float4*)&sA[i0 + r][d];
#pragma unroll
            for (int c = 0; c < 4; c++)
                acc[r][c] += qv.x * kc[0][c] + qv.y * kc[1][c] +
                             qv.z * kc[2][c] + qv.w * kc[3][c];
        }
    }

    const float* mrow = mask + ((size_t)b * 64) * 64;
    float p[4][4];
#pragma unroll
    for (int r = 0; r < 4; r++) {
        float4 mv = *(const float4*)(mrow + (size_t)(i0 + r) * 64 + j0);
        float s0 = acc[r][0] * 0.125f + __logf(mv.x + 1e-9f);
        float s1 = acc[r][1] * 0.125f + __logf(mv.y + 1e-9f);
        float s2 = acc[r][2] * 0.125f + __logf(mv.z + 1e-9f);
        float s3 = acc[r][3] * 0.125f + __logf(mv.w + 1e-9f);
        float mx = fmaxf(fmaxf(s0, s1), fmaxf(s2, s3));
        mx = fmaxf(mx, __shfl_xor_sync(0xffffffffu, mx, 1));
        mx = fmaxf(mx, __shfl_xor_sync(0xffffffffu, mx, 2));
        mx = fmaxf(mx, __shfl_xor_sync(0xffffffffu, mx, 4));
        mx = fmaxf(mx, __shfl_xor_sync(0xffffffffu, mx, 8));
        float e0 = __expf(s0 - mx), e1 = __expf(s1 - mx);
        float e2 = __expf(s2 - mx), e3 = __expf(s3 - mx);
        float sum = e0 + e1 + e2 + e3;
        sum += __shfl_xor_sync(0xffffffffu, sum, 1);
        sum += __shfl_xor_sync(0xffffffffu, sum, 2);
        sum += __shfl_xor_sync(0xffffffffu, sum, 4);
        sum += __shfl_xor_sync(0xffffffffu, sum, 8);
        const float inv = 1.0f / sum;
        p[r][0] = e0 * inv; p[r][1] = e1 * inv; p[r][2] = e2 * inv; p[r][3] = e3 * inv;
    }

    __syncthreads();

#pragma unroll
    for (int r = 0; r < 4; r++)
        *(float4*)&sA[i0 + r][j0] = make_float4(p[r][0], p[r][1], p[r][2], p[r][3]);
#pragma unroll
    for (int i = 0; i < 4; i++) {
        const int idx = t + 256 * i;
        const int row = idx >> 4;
        const int c4  = (idx & 15) * 4;
        *(float4*)&sB[row][c4] = *(const float4*)(g_v + base + (size_t)row * 512 + c4);
    }
    __syncthreads();

    float o[4][4];
#pragma unroll
    for (int r = 0; r < 4; r++)
#pragma unroll
        for (int c = 0; c < 4; c++) o[r][c] = 0.0f;

#pragma unroll
    for (int j = 0; j < 64; j += 4) {
        float vc[4][4];
#pragma unroll
        for (int jj = 0; jj < 4; jj++) {
            float4 vv = *(const float4*)&sB[j + jj][j0];
            vc[jj][0] = vv.x; vc[jj][1] = vv.y; vc[jj][2] = vv.z; vc[jj][3] = vv.w;
        }
#pragma unroll
        for (int r = 0; r < 4; r++) {
            float4 pv = *(const float4*)&sA[i0 + r][j];
#pragma unroll
            for (int c = 0; c < 4; c++)
                o[r][c] += pv.x * vc[0][c] + pv.y * vc[1][c] +
                           pv.z * vc[2][c] + pv.w * vc[3][c];
        }
    }

#pragma unroll
    for (int r = 0; r < 4; r++)
        *(float4*)(g_att + base + (size_t)(i0 + r) * 512 + j0) =
            make_float4(o[r][0], o[r][1], o[r][2], o[r][3]);
}

__global__ void tail_zero(float* __restrict__ out, long long start, long long total)
{
    long long i = start + (long long)blockIdx.x * blockDim.x + threadIdx.x;
    if (i < total) out[i] = 0.0f;
}

// ---------------------------------------------------------------------------
extern "C" void kernel_launch(void* const* d_in, const int* in_sizes, int n_in,
                              void* d_out, int out_size)
{
    const float* x    = (const float*)d_in[0];
    const float* mask = (const float*)d_in[1];
    const float* Wq   = (const float*)d_in[2];
    const float* bq   = (const float*)d_in[3];
    const float* Wk   = (const float*)d_in[4];
    const float* bk   = (const float*)d_in[5];
    const float* Wv   = (const float*)d_in[6];
    const float* bv   = (const float*)d_in[7];
    const float* Wo   = (const float*)d_in[8];
    const float* bo   = (const float*)d_in[9];
    float* out = (float*)d_out;

    // 0) Tail first (ccd_loss scalar / padding) — same order as R8 pass
    long long tail = (long long)out_size - OUT_ELEMS;
    if (tail > 0) {
        int blocks = (int)((tail + 255) / 256);
        tail_zero<<<blocks, 256>>>(out, OUT_ELEMS, (long long)out_size);
    }

    // 1) Fused QKV projections (grid.x = 12 -> {q,k,v} x 4 n-tiles of 128)
    gemm_f16<<<dim3(12, 1024), 256>>>(x, nullptr, Wq, Wk, Wv, bq, bk, bv, 0);

    // 2) Channel-masked attention
    attn_kernel<<<dim3(HEADS, BATCH), 256>>>(mask);

    // 3) Output projection (grid.x = 4)
    gemm_f16<<<dim3(4, 1024), 256>>>(nullptr, out, Wo, Wo, Wo, bo, bo, bo, 1);
}

// round 14
// speedup vs baseline: 1.3036x; 1.1020x over previous
#include <cuda_runtime.h>
#include <cstdint>

// Problem constants
#define BATCH 2048
#define SEQ   64
#define HEADS 8
#define M_ROWS (BATCH * SEQ)                  // 131072
#define OUT_ELEMS ((long long)M_ROWS * 512)   // 67108864

// Scratch (allocation-free rule: __device__ globals) — same four as R12 pass
__device__ __align__(16) float g_q[(size_t)M_ROWS * 512];
__device__ __align__(16) float g_k[(size_t)M_ROWS * 512];
__device__ __align__(16) float g_v[(size_t)M_ROWS * 512];
__device__ __align__(16) float g_att[(size_t)M_ROWS * 512];

// ---------------------------------------------------------------------------
// fp16 helpers
// ---------------------------------------------------------------------------
__device__ __forceinline__ uint32_t pack_h2(float lo, float hi) {
    // d.lo = second PTX source, d.hi = first
    uint32_t r;
    asm("cvt.rn.f16x2.f32 %0, %1, %2;" : "=r"(r) : "f"(hi), "f"(lo));
    return r;
}

__device__ __forceinline__ void mma_f16(float c[4], const uint32_t a[4],
                                        uint32_t b0, uint32_t b1) {
    asm volatile(
        "mma.sync.aligned.m16n8k16.row.col.f32.f16.f16.f32 "
        "{%0,%1,%2,%3}, {%4,%5,%6,%7}, {%8,%9}, {%0,%1,%2,%3};\n"
        : "+f"(c[0]), "+f"(c[1]), "+f"(c[2]), "+f"(c[3])
        : "r"(a[0]), "r"(a[1]), "r"(a[2]), "r"(a[3]), "r"(b0), "r"(b1));
}

// ---------------------------------------------------------------------------
// GEMM (byte-identical to R12 pass): C[M,512] = A[M,512] * W + bias
// ---------------------------------------------------------------------------
#define APITCH 24
#define BPITCH 136
#define A_WORDS (128 * APITCH)   // 3072
#define B_WORDS (16 * BPITCH)    // 2176

__global__ __launch_bounds__(256, 2)
void gemm_f16(const float* __restrict__ X, float* __restrict__ Cout,
              const float* __restrict__ W0, const float* __restrict__ W1,
              const float* __restrict__ W2,
              const float* __restrict__ bias0, const float* __restrict__ bias1,
              const float* __restrict__ bias2, int mode)
{
    __shared__ uint32_t Asm[2][A_WORDS];
    __shared__ uint32_t Bsm[2][B_WORDS];

    const int t  = threadIdx.x;
    const int m0 = blockIdx.y * 128;

    const float* A; const float* W; const float* bias; float* C; int n0;
    if (mode == 0) {
        const int mat = blockIdx.x >> 2;
        n0 = (blockIdx.x & 3) * 128;
        A = X;
        W    = (mat == 0) ? W0 : (mat == 1) ? W1 : W2;
        bias = (mat == 0) ? bias0 : (mat == 1) ? bias1 : bias2;
        C    = (mat == 0) ? g_q : (mat == 1) ? g_k : g_v;
    } else {
        n0 = blockIdx.x * 128;
        A = g_att; W = W0; bias = bias0; C = Cout;
    }

    const int arow = t >> 1;
    const int ah   = t & 1;
    const int kkr  = t >> 4;
    const int nc   = (t & 15) * 8;

    const float* Ap  = A + (size_t)(m0 + arow) * 512 + ah * 16;
    const float* Bp0 = W + (size_t)(2 * kkr)     * 512 + n0 + nc;
    const float* Bp1 = W + (size_t)(2 * kkr + 1) * 512 + n0 + nc;

    const int w = t >> 5, lane = t & 31;
    const int gid = lane >> 2, tig = lane & 3;
    const int wm = (w & 3) * 32;
    const int wn = (w >> 2) * 64;

    float acc[2][8][4];
#pragma unroll
    for (int mi = 0; mi < 2; mi++)
#pragma unroll
        for (int nj = 0; nj < 8; nj++)
#pragma unroll
            for (int c = 0; c < 4; c++) acc[mi][nj][c] = 0.0f;

    float4 ra[4], rb[4];
#pragma unroll
    for (int j = 0; j < 4; j++) ra[j] = *(const float4*)(Ap + j * 4);
#pragma unroll
    for (int j = 0; j < 2; j++) {
        rb[j]     = *(const float4*)(Bp0 + j * 4);
        rb[2 + j] = *(const float4*)(Bp1 + j * 4);
    }
    {
        uint32_t wv[8];
#pragma unroll
        for (int j = 0; j < 4; j++) {
            wv[2 * j]     = pack_h2(ra[j].x, ra[j].y);
            wv[2 * j + 1] = pack_h2(ra[j].z, ra[j].w);
        }
        *(uint4*)&Asm[0][arow * APITCH + ah * 8]     = make_uint4(wv[0], wv[4], wv[1], wv[5]);
        *(uint4*)&Asm[0][arow * APITCH + ah * 8 + 4] = make_uint4(wv[2], wv[6], wv[3], wv[7]);
#pragma unroll
        for (int j = 0; j < 2; j++) {
            const float* lo = (const float*)&rb[j];
            const float* hi = (const float*)&rb[2 + j];
            uint4 u = make_uint4(pack_h2(lo[0], hi[0]), pack_h2(lo[1], hi[1]),
                                 pack_h2(lo[2], hi[2]), pack_h2(lo[3], hi[3]));
            *(uint4*)&Bsm[0][kkr * BPITCH + nc + 4 * j] = u;
        }
    }
    __syncthreads();

    for (int kt = 0; kt < 16; kt++) {
        const int cb = kt & 1;
        if (kt < 15) {
            const float* Ap2  = Ap + (kt + 1) * 32;
            const float* Bp02 = Bp0 + (size_t)((kt + 1) * 32) * 512;
            const float* Bp12 = Bp1 + (size_t)((kt + 1) * 32) * 512;
#pragma unroll
            for (int j = 0; j < 4; j++) ra[j] = *(const float4*)(Ap2 + j * 4);
#pragma unroll
            for (int j = 0; j < 2; j++) {
                rb[j]     = *(const float4*)(Bp02 + j * 4);
                rb[2 + j] = *(const float4*)(Bp12 + j * 4);
            }
        }

        const uint32_t* as = Asm[cb];
        const uint32_t* bs = Bsm[cb];
#pragma unroll
        for (int ks = 0; ks < 2; ks++) {
            const int kb = ks * 8;
            const int kw = kb + tig * 2;
            uint32_t a[2][4];
#pragma unroll
            for (int mi = 0; mi < 2; mi++) {
                const int r = wm + mi * 16 + gid;
                const uint2 lo = *(const uint2*)(as + r * APITCH + kw);
                const uint2 hi = *(const uint2*)(as + (r + 8) * APITCH + kw);
                a[mi][0] = lo.x; a[mi][1] = hi.x; a[mi][2] = lo.y; a[mi][3] = hi.y;
            }
#pragma unroll
            for (int nj = 0; nj < 8; nj++) {
                const int c = wn + nj * 8 + gid;
                const uint32_t b0 = bs[(kb + tig) * BPITCH + c];
                const uint32_t b1 = bs[(kb + 4 + tig) * BPITCH + c];
                mma_f16(acc[0][nj], a[0], b0, b1);
                mma_f16(acc[1][nj], a[1], b0, b1);
            }
        }

        if (kt < 15) {
            const int nb = cb ^ 1;
            uint32_t wv[8];
#pragma unroll
            for (int j = 0; j < 4; j++) {
                wv[2 * j]     = pack_h2(ra[j].x, ra[j].y);
                wv[2 * j + 1] = pack_h2(ra[j].z, ra[j].w);
            }
            *(uint4*)&Asm[nb][arow * APITCH + ah * 8]     = make_uint4(wv[0], wv[4], wv[1], wv[5]);
            *(uint4*)&Asm[nb][arow * APITCH + ah * 8 + 4] = make_uint4(wv[2], wv[6], wv[3], wv[7]);
#pragma unroll
            for (int j = 0; j < 2; j++) {
                const float* lo = (const float*)&rb[j];
                const float* hi = (const float*)&rb[2 + j];
                uint4 u = make_uint4(pack_h2(lo[0], hi[0]), pack_h2(lo[1], hi[1]),
                                     pack_h2(lo[2], hi[2]), pack_h2(lo[3], hi[3]));
                *(uint4*)&Bsm[nb][kkr * BPITCH + nc + 4 * j] = u;
            }
        }
        __syncthreads();
    }

#pragma unroll
    for (int mi = 0; mi < 2; mi++) {
#pragma unroll
        for (int nj = 0; nj < 8; nj++) {
            const int row = m0 + wm + mi * 16 + gid;
            const int col = n0 + wn + nj * 8 + tig * 2;
            const float2 bv = *(const float2*)(bias + col);
            *(float2*)(C + (size_t)row * 512 + col) =
                make_float2(acc[mi][nj][0] + bv.x, acc[mi][nj][1] + bv.y);
            *(float2*)(C + (size_t)(row + 8) * 512 + col) =
                make_float2(acc[mi][nj][2] + bv.x, acc[mi][nj][3] + bv.y);
        }
    }
}

// ---------------------------------------------------------------------------
// Attention v2: tensor-core mma, one block (128 thr = 4 warps) per (b,h).
// Reuses the GEMM's proven fragment algebra:
//   Q  -> A-layout (pair-interleaved, pitch 40; conflict-free LDS.64)
//   K,V-> B-word layout (X[2kk][c], X[2kk+1][c]), pitch 72 (full-warp c-f)
//   S accum fragment IS the PV A-fragment (flash-attn register reuse)
// One __syncthreads; softmax reduced over the 4-lane tig group.
// ---------------------------------------------------------------------------
#define QPITCH 40
#define KVPITCH 72

__global__ __launch_bounds__(128)
void attn_mma(const float* __restrict__ mask)
{
    __shared__ uint32_t sQ[64 * QPITCH];    // 10240 B
    __shared__ uint32_t sK[32 * KVPITCH];   //  9216 B
    __shared__ uint32_t sV[32 * KVPITCH];   //  9216 B
    __shared__ float    sM[64 * 68];        // 17408 B   (total 46080)

    const int b = blockIdx.y;
    const int h = blockIdx.x;
    const int t = threadIdx.x;
    const size_t base = ((size_t)b * 64) * 512 + (size_t)h * 64;

    // ---- stage Q (A-layout; verbatim R12 word order) ----
    {
        const int row = t >> 1, ch = t & 1;
        const float* src = g_q + base + (size_t)row * 512 + ch * 32;
        uint32_t* dq = sQ + row * QPITCH + ch * 16;
#pragma unroll
        for (int g = 0; g < 2; g++) {
            float4 f0 = *(const float4*)(src + g * 16);
            float4 f1 = *(const float4*)(src + g * 16 + 4);
            float4 f2 = *(const float4*)(src + g * 16 + 8);
            float4 f3 = *(const float4*)(src + g * 16 + 12);
            uint32_t q0 = pack_h2(f0.x, f0.y), q1 = pack_h2(f0.z, f0.w);
            uint32_t q2 = pack_h2(f1.x, f1.y), q3 = pack_h2(f1.z, f1.w);
            uint32_t q4 = pack_h2(f2.x, f2.y), q5 = pack_h2(f2.z, f2.w);
            uint32_t q6 = pack_h2(f3.x, f3.y), q7 = pack_h2(f3.z, f3.w);
            *(uint4*)(dq + g * 8)     = make_uint4(q0, q4, q1, q5);
            *(uint4*)(dq + g * 8 + 4) = make_uint4(q2, q6, q3, q7);
        }
    }
    // ---- stage K (transpose-scatter into B-word layout) ----
    {
        const int j = t >> 1, dh = (t & 1) * 32;
        const float* src = g_k + base + (size_t)j * 512 + dh;
        float f[32];
#pragma unroll
        for (int g = 0; g < 8; g++) *(float4*)&f[4 * g] = *(const float4*)(src + 4 * g);
        const int kk0 = dh >> 1;
#pragma unroll
        for (int p = 0; p < 16; p++)
            sK[(kk0 + p) * KVPITCH + j] = pack_h2(f[2 * p], f[2 * p + 1]);
    }
    // ---- stage V (B-word layout, row-pair pack; GEMM-B pattern) ----
    {
        const int kk = t >> 2, nb = (t & 3) * 16;
        const float* vlo = g_v + base + (size_t)(2 * kk) * 512 + nb;
        const float* vhi = vlo + 512;
        uint32_t* dv = sV + kk * KVPITCH + nb;
#pragma unroll
        for (int g = 0; g < 4; g++) {
            float4 lo = *(const float4*)(vlo + 4 * g);
            float4 hi = *(const float4*)(vhi + 4 * g);
            *(uint4*)(dv + 4 * g) = make_uint4(pack_h2(lo.x, hi.x), pack_h2(lo.y, hi.y),
                                               pack_h2(lo.z, hi.z), pack_h2(lo.w, hi.w));
        }
    }
    // ---- stage mask tile ----
    {
        const int row = t >> 1, cm = (t & 1) * 32;
        const float* src = mask + (size_t)b * 4096 + row * 64 + cm;
        float* dm = sM + row * 68 + cm;
#pragma unroll
        for (int g = 0; g < 8; g++) *(float4*)(dm + 4 * g) = *(const float4*)(src + 4 * g);
    }
    __syncthreads();

    const int wq = t >> 5, lane = t & 31;
    const int gid = lane >> 2, tig = lane & 3;
    const int r0 = wq * 16 + gid;            // warp rows r0, r0+8

    // ---- S = Q K^T ----
    float sacc[8][4];
#pragma unroll
    for (int nj = 0; nj < 8; nj++)
#pragma unroll
        for (int c = 0; c < 4; c++) sacc[nj][c] = 0.0f;

#pragma unroll
    for (int KS = 0; KS < 4; KS++) {
        const int kw = KS * 8 + tig * 2;
        const uint2 lo = *(const uint2*)(sQ + r0 * QPITCH + kw);
        const uint2 hi = *(const uint2*)(sQ + (r0 + 8) * QPITCH + kw);
        uint32_t a[4] = { lo.x, hi.x, lo.y, hi.y };
#pragma unroll
        for (int nj = 0; nj < 8; nj++) {
            const int c = nj * 8 + gid;
            const uint32_t b0 = sK[(KS * 8 + tig) * KVPITCH + c];
            const uint32_t b1 = sK[(KS * 8 + 4 + tig) * KVPITCH + c];
            mma_f16(sacc[nj], a, b0, b1);
        }
    }

    // ---- masked softmax (rows r0 and r0+8; reduce over tig group) ----
    float mx0 = -1e30f, mx1 = -1e30f;
#pragma unroll
    for (int nj = 0; nj < 8; nj++) {
        const float2 m0 = *(const float2*)(sM + r0 * 68 + nj * 8 + 2 * tig);
        const float2 m1 = *(const float2*)(sM + (r0 + 8) * 68 + nj * 8 + 2 * tig);
        sacc[nj][0] = sacc[nj][0] * 0.125f + __logf(m0.x + 1e-9f);
        sacc[nj][1] = sacc[nj][1] * 0.125f + __logf(m0.y + 1e-9f);
        sacc[nj][2] = sacc[nj][2] * 0.125f + __logf(m1.x + 1e-9f);
        sacc[nj][3] = sacc[nj][3] * 0.125f + __logf(m1.y + 1e-9f);
        mx0 = fmaxf(mx0, fmaxf(sacc[nj][0], sacc[nj][1]));
        mx1 = fmaxf(mx1, fmaxf(sacc[nj][2], sacc[nj][3]));
    }
    mx0 = fmaxf(mx0, __shfl_xor_sync(0xffffffffu, mx0, 1));
    mx0 = fmaxf(mx0, __shfl_xor_sync(0xffffffffu, mx0, 2));
    mx1 = fmaxf(mx1, __shfl_xor_sync(0xffffffffu, mx1, 1));
    mx1 = fmaxf(mx1, __shfl_xor_sync(0xffffffffu, mx1, 2));

    float sum0 = 0.0f, sum1 = 0.0f;
#pragma unroll
    for (int nj = 0; nj < 8; nj++) {
        sacc[nj][0] = __expf(sacc[nj][0] - mx0);
        sacc[nj][1] = __expf(sacc[nj][1] - mx0);
        sacc[nj][2] = __expf(sacc[nj][2] - mx1);
        sacc[nj][3] = __expf(sacc[nj][3] - mx1);
        sum0 += sacc[nj][0] + sacc[nj][1];
        sum1 += sacc[nj][2] + sacc[nj][3];
    }
    sum0 += __shfl_xor_sync(0xffffffffu, sum0, 1);
    sum0 += __shfl_xor_sync(0xffffffffu, sum0, 2);
    sum1 += __shfl_xor_sync(0xffffffffu, sum1, 1);
    sum1 += __shfl_xor_sync(0xffffffffu, sum1, 2);
    const float inv0 = 1.0f / sum0, inv1 = 1.0f / sum1;
#pragma unroll
    for (int nj = 0; nj < 8; nj++) {
        sacc[nj][0] *= inv0; sacc[nj][1] *= inv0;
        sacc[nj][2] *= inv1; sacc[nj][3] *= inv1;
    }

    // ---- O = P V  (P fragments direct from sacc registers) ----
    float oacc[8][4];
#pragma unroll
    for (int nd = 0; nd < 8; nd++)
#pragma unroll
        for (int c = 0; c < 4; c++) oacc[nd][c] = 0.0f;

#pragma unroll
    for (int JS = 0; JS < 4; JS++) {
        uint32_t a[4];
        a[0] = pack_h2(sacc[2 * JS][0],     sacc[2 * JS][1]);
        a[1] = pack_h2(sacc[2 * JS][2],     sacc[2 * JS][3]);
        a[2] = pack_h2(sacc[2 * JS + 1][0], sacc[2 * JS + 1][1]);
        a[3] = pack_h2(sacc[2 * JS + 1][2], sacc[2 * JS + 1][3]);
#pragma unroll
        for (int nd = 0; nd < 8; nd++) {
            const int c = nd * 8 + gid;
            const uint32_t b0 = sV[(JS * 8 + tig) * KVPITCH + c];
            const uint32_t b1 = sV[(JS * 8 + 4 + tig) * KVPITCH + c];
            mma_f16(oacc[nd], a, b0, b1);
        }
    }

    // ---- epilogue (GEMM-proven float2 pattern) ----
    const int grow = b * 64 + r0;
#pragma unroll
    for (int nd = 0; nd < 8; nd++) {
        const int col = h * 64 + nd * 8 + tig * 2;
        *(float2*)(g_att + (size_t)grow * 512 + col) =
            make_float2(oacc[nd][0], oacc[nd][1]);
        *(float2*)(g_att + (size_t)(grow + 8) * 512 + col) =
            make_float2(oacc[nd][2], oacc[nd][3]);
    }
}

__global__ void tail_zero(float* __restrict__ out, long long start, long long total)
{
    long long i = start + (long long)blockIdx.x * blockDim.x + threadIdx.x;
    if (i < total) out[i] = 0.0f;
}

// ---------------------------------------------------------------------------
extern "C" void kernel_launch(void* const* d_in, const int* in_sizes, int n_in,
                              void* d_out, int out_size)
{
    const float* x    = (const float*)d_in[0];
    const float* mask = (const float*)d_in[1];
    const float* Wq   = (const float*)d_in[2];
    const float* bq   = (const float*)d_in[3];
    const float* Wk   = (const float*)d_in[4];
    const float* bk   = (const float*)d_in[5];
    const float* Wv   = (const float*)d_in[6];
    const float* bv   = (const float*)d_in[7];
    const float* Wo   = (const float*)d_in[8];
    const float* bo   = (const float*)d_in[9];
    float* out = (float*)d_out;

    // 0) Tail first (ccd_loss scalar / padding)
    long long tail = (long long)out_size - OUT_ELEMS;
    if (tail > 0) {
        int blocks = (int)((tail + 255) / 256);
        tail_zero<<<blocks, 256>>>(out, OUT_ELEMS, (long long)out_size);
    }

    // 1) Fused QKV projections (grid.x = 12 -> {q,k,v} x 4 n-tiles of 128)
    gemm_f16<<<dim3(12, 1024), 256>>>(x, nullptr, Wq, Wk, Wv, bq, bk, bv, 0);

    // 2) Channel-masked attention (tensor-core version)
    attn_mma<<<dim3(HEADS, BATCH), 128>>>(mask);

    // 3) Output projection (grid.x = 4)
    gemm_f16<<<dim3(4, 1024), 256>>>(nullptr, out, Wo, Wo, Wo, bo, bo, bo, 1);
}

// round 15
// speedup vs baseline: 1.3445x; 1.0314x over previous
#include <cuda_runtime.h>
#include <cuda_fp16.h>
#include <cstdint>

// Problem constants
#define BATCH 2048
#define SEQ   64
#define HEADS 8
#define M_ROWS (BATCH * SEQ)                  // 131072
#define OUT_ELEMS ((long long)M_ROWS * 512)   // 67108864

// Scratch (allocation-free rule: __device__ globals) — same 4 names, now fp16
__device__ __align__(16) __half g_q[(size_t)M_ROWS * 512];
__device__ __align__(16) __half g_k[(size_t)M_ROWS * 512];
__device__ __align__(16) __half g_v[(size_t)M_ROWS * 512];
__device__ __align__(16) __half g_att[(size_t)M_ROWS * 512];

// ---------------------------------------------------------------------------
// fp16 helpers
// ---------------------------------------------------------------------------
__device__ __forceinline__ uint32_t pack_h2(float lo, float hi) {
    // d.lo = second PTX source, d.hi = first
    uint32_t r;
    asm("cvt.rn.f16x2.f32 %0, %1, %2;" : "=r"(r) : "f"(hi), "f"(lo));
    return r;
}

__device__ __forceinline__ void mma_f16(float c[4], const uint32_t a[4],
                                        uint32_t b0, uint32_t b1) {
    asm volatile(
        "mma.sync.aligned.m16n8k16.row.col.f32.f16.f16.f32 "
        "{%0,%1,%2,%3}, {%4,%5,%6,%7}, {%8,%9}, {%0,%1,%2,%3};\n"
        : "+f"(c[0]), "+f"(c[1]), "+f"(c[2]), "+f"(c[3])
        : "r"(a[0]), "r"(a[1]), "r"(a[2]), "r"(a[3]), "r"(b0), "r"(b1));
}

// ---------------------------------------------------------------------------
// GEMM: C[M,512] = A[M,512] * W[512,512] + bias   (fp16 mma.sync, fp32 accum)
// R13-proven skeleton. Deltas: mode-0 epilogue stores half2 into g_q/g_k/g_v;
// mode-1 A operand is fp16 (g_att) — staging reads packed half words directly.
// ---------------------------------------------------------------------------
#define APITCH 24
#define BPITCH 136
#define A_WORDS (128 * APITCH)   // 3072
#define B_WORDS (16 * BPITCH)    // 2176

__global__ __launch_bounds__(256, 2)
void gemm_f16(const float* __restrict__ X, float* __restrict__ Cout,
              const float* __restrict__ W0, const float* __restrict__ W1,
              const float* __restrict__ W2,
              const float* __restrict__ bias0, const float* __restrict__ bias1,
              const float* __restrict__ bias2, int mode)
{
    __shared__ uint32_t Asm[2][A_WORDS];
    __shared__ uint32_t Bsm[2][B_WORDS];

    const int t  = threadIdx.x;
    const int m0 = blockIdx.y * 128;

    const float* W; const float* bias; __half* Ch = nullptr; float* Cf = nullptr; int n0;
    if (mode == 0) {
        const int mat = blockIdx.x >> 2;
        n0 = (blockIdx.x & 3) * 128;
        W    = (mat == 0) ? W0 : (mat == 1) ? W1 : W2;
        bias = (mat == 0) ? bias0 : (mat == 1) ? bias1 : bias2;
        Ch   = (mat == 0) ? g_q : (mat == 1) ? g_k : g_v;
    } else {
        n0 = blockIdx.x * 128;
        W = W0; bias = bias0; Cf = Cout;
    }

    // staging maps (proven)
    const int arow = t >> 1;           // 0..127
    const int ah   = t & 1;            // halves of the 32-k chunk
    const int kkr  = t >> 4;           // 0..15 (packed-k row of B)
    const int nc   = (t & 15) * 8;     // n col 0..120

    const float*  Apf = X     + (size_t)(m0 + arow) * 512 + ah * 16;   // mode 0
    const __half* Aph = g_att + (size_t)(m0 + arow) * 512 + ah * 16;   // mode 1
    const float* Bp0 = W + (size_t)(2 * kkr)     * 512 + n0 + nc;
    const float* Bp1 = W + (size_t)(2 * kkr + 1) * 512 + n0 + nc;

    // warp mapping (proven): 4 (m) x 2 (n), warp tile 32x64
    const int w = t >> 5, lane = t & 31;
    const int gid = lane >> 2, tig = lane & 3;
    const int wm = (w & 3) * 32;
    const int wn = (w >> 2) * 64;

    float acc[2][8][4];
#pragma unroll
    for (int mi = 0; mi < 2; mi++)
#pragma unroll
        for (int nj = 0; nj < 8; nj++)
#pragma unroll
            for (int c = 0; c < 4; c++) acc[mi][nj][c] = 0.0f;

    float4 ra[4];          // mode-0 A prefetch
    uint4  ua0, ua1;       // mode-1 A prefetch (8 packed words)
    float4 rb[4];

    // prologue: load kt=0 and stage into buf 0
    if (mode == 0) {
#pragma unroll
        for (int j = 0; j < 4; j++) ra[j] = *(const float4*)(Apf + j * 4);
    } else {
        ua0 = *(const uint4*)(Aph);
        ua1 = *(const uint4*)(Aph + 8);
    }
#pragma unroll
    for (int j = 0; j < 2; j++) {
        rb[j]     = *(const float4*)(Bp0 + j * 4);
        rb[2 + j] = *(const float4*)(Bp1 + j * 4);
    }
    {
        if (mode == 0) {
            uint32_t wv[8];
#pragma unroll
            for (int j = 0; j < 4; j++) {
                wv[2 * j]     = pack_h2(ra[j].x, ra[j].y);
                wv[2 * j + 1] = pack_h2(ra[j].z, ra[j].w);
            }
            *(uint4*)&Asm[0][arow * APITCH + ah * 8]     = make_uint4(wv[0], wv[4], wv[1], wv[5]);
            *(uint4*)&Asm[0][arow * APITCH + ah * 8 + 4] = make_uint4(wv[2], wv[6], wv[3], wv[7]);
        } else {
            // ua0 = words(pairs 0..3), ua1 = words(pairs 4..7); same interleave
            *(uint4*)&Asm[0][arow * APITCH + ah * 8]     = make_uint4(ua0.x, ua1.x, ua0.y, ua1.y);
            *(uint4*)&Asm[0][arow * APITCH + ah * 8 + 4] = make_uint4(ua0.z, ua1.z, ua0.w, ua1.w);
        }
#pragma unroll
        for (int j = 0; j < 2; j++) {
            const float* lo = (const float*)&rb[j];
            const float* hi = (const float*)&rb[2 + j];
            uint4 u = make_uint4(pack_h2(lo[0], hi[0]), pack_h2(lo[1], hi[1]),
                                 pack_h2(lo[2], hi[2]), pack_h2(lo[3], hi[3]));
            *(uint4*)&Bsm[0][kkr * BPITCH + nc + 4 * j] = u;
        }
    }
    __syncthreads();

    for (int kt = 0; kt < 16; kt++) {
        const int cb = kt & 1;
        if (kt < 15) {
            if (mode == 0) {
                const float* Ap2 = Apf + (kt + 1) * 32;
#pragma unroll
                for (int j = 0; j < 4; j++) ra[j] = *(const float4*)(Ap2 + j * 4);
            } else {
                const __half* Ah2 = Aph + (kt + 1) * 32;
                ua0 = *(const uint4*)(Ah2);
                ua1 = *(const uint4*)(Ah2 + 8);
            }
            const float* Bp02 = Bp0 + (size_t)((kt + 1) * 32) * 512;
            const float* Bp12 = Bp1 + (size_t)((kt + 1) * 32) * 512;
#pragma unroll
            for (int j = 0; j < 2; j++) {
                rb[j]     = *(const float4*)(Bp02 + j * 4);
                rb[2 + j] = *(const float4*)(Bp12 + j * 4);
            }
        }

        const uint32_t* as = Asm[cb];
        const uint32_t* bs = Bsm[cb];
#pragma unroll
        for (int ks = 0; ks < 2; ks++) {
            const int kb = ks * 8;
            const int kw = kb + tig * 2;
            uint32_t a[2][4];
#pragma unroll
            for (int mi = 0; mi < 2; mi++) {
                const int r = wm + mi * 16 + gid;
                const uint2 lo = *(const uint2*)(as + r * APITCH + kw);
                const uint2 hi = *(const uint2*)(as + (r + 8) * APITCH + kw);
                a[mi][0] = lo.x; a[mi][1] = hi.x; a[mi][2] = lo.y; a[mi][3] = hi.y;
            }
#pragma unroll
            for (int nj = 0; nj < 8; nj++) {
                const int c = wn + nj * 8 + gid;
                const uint32_t b0 = bs[(kb + tig) * BPITCH + c];
                const uint32_t b1 = bs[(kb + 4 + tig) * BPITCH + c];
                mma_f16(acc[0][nj], a[0], b0, b1);
                mma_f16(acc[1][nj], a[1], b0, b1);
            }
        }

        if (kt < 15) {
            const int nb = cb ^ 1;
            if (mode == 0) {
                uint32_t wv[8];
#pragma unroll
                for (int j = 0; j < 4; j++) {
                    wv[2 * j]     = pack_h2(ra[j].x, ra[j].y);
                    wv[2 * j + 1] = pack_h2(ra[j].z, ra[j].w);
                }
                *(uint4*)&Asm[nb][arow * APITCH + ah * 8]     = make_uint4(wv[0], wv[4], wv[1], wv[5]);
                *(uint4*)&Asm[nb][arow * APITCH + ah * 8 + 4] = make_uint4(wv[2], wv[6], wv[3], wv[7]);
            } else {
                *(uint4*)&Asm[nb][arow * APITCH + ah * 8]     = make_uint4(ua0.x, ua1.x, ua0.y, ua1.y);
                *(uint4*)&Asm[nb][arow * APITCH + ah * 8 + 4] = make_uint4(ua0.z, ua1.z, ua0.w, ua1.w);
            }
#pragma unroll
            for (int j = 0; j < 2; j++) {
                const float* lo = (const float*)&rb[j];
                const float* hi = (const float*)&rb[2 + j];
                uint4 u = make_uint4(pack_h2(lo[0], hi[0]), pack_h2(lo[1], hi[1]),
                                     pack_h2(lo[2], hi[2]), pack_h2(lo[3], hi[3]));
                *(uint4*)&Bsm[nb][kkr * BPITCH + nc + 4 * j] = u;
            }
        }
        __syncthreads();
    }

    // epilogue: bias; mode 0 -> half2 stores, mode 1 -> float2 stores
#pragma unroll
    for (int mi = 0; mi < 2; mi++) {
#pragma unroll
        for (int nj = 0; nj < 8; nj++) {
            const int row = m0 + wm + mi * 16 + gid;
            const int col = n0 + wn + nj * 8 + tig * 2;
            const float2 bv = *(const float2*)(bias + col);
            const float v0 = acc[mi][nj][0] + bv.x, v1 = acc[mi][nj][1] + bv.y;
            const float v2 = acc[mi][nj][2] + bv.x, v3 = acc[mi][nj][3] + bv.y;
            if (mode == 0) {
                *(uint32_t*)(Ch + (size_t)row * 512 + col)       = pack_h2(v0, v1);
                *(uint32_t*)(Ch + (size_t)(row + 8) * 512 + col) = pack_h2(v2, v3);
            } else {
                *(float2*)(Cf + (size_t)row * 512 + col)       = make_float2(v0, v1);
                *(float2*)(Cf + (size_t)(row + 8) * 512 + col) = make_float2(v2, v3);
            }
        }
    }
}

// ---------------------------------------------------------------------------
// Attention (R13-proven mma core): fp16 staging is now pure word shuffles.
// ---------------------------------------------------------------------------
#define QPITCH 40
#define KVPITCH 72

__global__ __launch_bounds__(128)
void attn_mma(const float* __restrict__ mask)
{
    __shared__ uint32_t sQ[64 * QPITCH];
    __shared__ uint32_t sK[32 * KVPITCH];
    __shared__ uint32_t sV[32 * KVPITCH];
    __shared__ float    sM[64 * 68];

    const int b = blockIdx.y;
    const int h = blockIdx.x;
    const int t = threadIdx.x;
    const size_t base = ((size_t)b * 64) * 512 + (size_t)h * 64;

    // ---- stage Q (A-interleave; direct word copies) ----
    {
        const int row = t >> 1, ch = t & 1;
        const __half* src = g_q + base + (size_t)row * 512 + ch * 32;
        uint32_t* dq = sQ + row * QPITCH + ch * 16;
#pragma unroll
        for (int g = 0; g < 2; g++) {
            uint4 u0 = *(const uint4*)(src + g * 16);       // words: pairs g*8+0..3
            uint4 u1 = *(const uint4*)(src + g * 16 + 8);   // words: pairs g*8+4..7
            *(uint4*)(dq + g * 8)     = make_uint4(u0.x, u1.x, u0.y, u1.y);
            *(uint4*)(dq + g * 8 + 4) = make_uint4(u0.z, u1.z, u0.w, u1.w);
        }
    }
    // ---- stage K (word transpose-scatter; no cvt) ----
    {
        const int j = t >> 1, dh = (t & 1) * 32;
        const __half* src = g_k + base + (size_t)j * 512 + dh;
        uint32_t wds[16];
#pragma unroll
        for (int g = 0; g < 4; g++) *(uint4*)&wds[4 * g] = *(const uint4*)(src + 8 * g);
        const int kk0 = dh >> 1;
#pragma unroll
        for (int p = 0; p < 16; p++)
            sK[(kk0 + p) * KVPITCH + j] = wds[p];
    }
    // ---- stage V (lo/hi merge of two rows via byte_perm) ----
    {
        const int kk = t >> 2, nb = (t & 3) * 16;
        const __half* vlo = g_v + base + (size_t)(2 * kk) * 512 + nb;
        const __half* vhi = vlo + 512;
        uint32_t L[8], H[8];
        *(uint4*)&L[0] = *(const uint4*)(vlo);
        *(uint4*)&L[4] = *(const uint4*)(vlo + 8);
        *(uint4*)&H[0] = *(const uint4*)(vhi);
        *(uint4*)&H[4] = *(const uint4*)(vhi + 8);
        uint32_t* dv = sV + kk * KVPITCH + nb;
        uint32_t o[16];
#pragma unroll
        for (int j = 0; j < 8; j++) {
            o[2 * j]     = __byte_perm(L[j], H[j], 0x5410);  // (L.lo, H.lo)
            o[2 * j + 1] = __byte_perm(L[j], H[j], 0x7632);  // (L.hi, H.hi)
        }
#pragma unroll
        for (int g = 0; g < 4; g++) *(uint4*)(dv + 4 * g) = *(uint4*)&o[4 * g];
    }
    // ---- stage mask tile ----
    {
        const int row = t >> 1, cm = (t & 1) * 32;
        const float* src = mask + (size_t)b * 4096 + row * 64 + cm;
        float* dm = sM + row * 68 + cm;
#pragma unroll
        for (int g = 0; g < 8; g++) *(float4*)(dm + 4 * g) = *(const float4*)(src + 4 * g);
    }
    __syncthreads();

    const int wq = t >> 5, lane = t & 31;
    const int gid = lane >> 2, tig = lane & 3;
    const int r0 = wq * 16 + gid;

    // ---- S = Q K^T ----
    float sacc[8][4];
#pragma unroll
    for (int nj = 0; nj < 8; nj++)
#pragma unroll
        for (int c = 0; c < 4; c++) sacc[nj][c] = 0.0f;

#pragma unroll
    for (int KS = 0; KS < 4; KS++) {
        const int kw = KS * 8 + tig * 2;
        const uint2 lo = *(const uint2*)(sQ + r0 * QPITCH + kw);
        const uint2 hi = *(const uint2*)(sQ + (r0 + 8) * QPITCH + kw);
        uint32_t a[4] = { lo.x, hi.x, lo.y, hi.y };
#pragma unroll
        for (int nj = 0; nj < 8; nj++) {
            const int c = nj * 8 + gid;
            const uint32_t b0 = sK[(KS * 8 + tig) * KVPITCH + c];
            const uint32_t b1 = sK[(KS * 8 + 4 + tig) * KVPITCH + c];
            mma_f16(sacc[nj], a, b0, b1);
        }
    }

    // ---- masked softmax ----
    float mx0 = -1e30f, mx1 = -1e30f;
#pragma unroll
    for (int nj = 0; nj < 8; nj++) {
        const float2 m0 = *(const float2*)(sM + r0 * 68 + nj * 8 + 2 * tig);
        const float2 m1 = *(const float2*)(sM + (r0 + 8) * 68 + nj * 8 + 2 * tig);
        sacc[nj][0] = sacc[nj][0] * 0.125f + __logf(m0.x + 1e-9f);
        sacc[nj][1] = sacc[nj][1] * 0.125f + __logf(m0.y + 1e-9f);
        sacc[nj][2] = sacc[nj][2] * 0.125f + __logf(m1.x + 1e-9f);
        sacc[nj][3] = sacc[nj][3] * 0.125f + __logf(m1.y + 1e-9f);
        mx0 = fmaxf(mx0, fmaxf(sacc[nj][0], sacc[nj][1]));
        mx1 = fmaxf(mx1, fmaxf(sacc[nj][2], sacc[nj][3]));
    }
    mx0 = fmaxf(mx0, __shfl_xor_sync(0xffffffffu, mx0, 1));
    mx0 = fmaxf(mx0, __shfl_xor_sync(0xffffffffu, mx0, 2));
    mx1 = fmaxf(mx1, __shfl_xor_sync(0xffffffffu, mx1, 1));
    mx1 = fmaxf(mx1, __shfl_xor_sync(0xffffffffu, mx1, 2));

    float sum0 = 0.0f, sum1 = 0.0f;
#pragma unroll
    for (int nj = 0; nj < 8; nj++) {
        sacc[nj][0] = __expf(sacc[nj][0] - mx0);
        sacc[nj][1] = __expf(sacc[nj][1] - mx0);
        sacc[nj][2] = __expf(sacc[nj][2] - mx1);
        sacc[nj][3] = __expf(sacc[nj][3] - mx1);
        sum0 += sacc[nj][0] + sacc[nj][1];
        sum1 += sacc[nj][2] + sacc[nj][3];
    }
    sum0 += __shfl_xor_sync(0xffffffffu, sum0, 1);
    sum0 += __shfl_xor_sync(0xffffffffu, sum0, 2);
    sum1 += __shfl_xor_sync(0xffffffffu, sum1, 1);
    sum1 += __shfl_xor_sync(0xffffffffu, sum1, 2);
    const float inv0 = 1.0f / sum0, inv1 = 1.0f / sum1;
#pragma unroll
    for (int nj = 0; nj < 8; nj++) {
        sacc[nj][0] *= inv0; sacc[nj][1] *= inv0;
        sacc[nj][2] *= inv1; sacc[nj][3] *= inv1;
    }

    // ---- O = P V ----
    float oacc[8][4];
#pragma unroll
    for (int nd = 0; nd < 8; nd++)
#pragma unroll
        for (int c = 0; c < 4; c++) oacc[nd][c] = 0.0f;

#pragma unroll
    for (int JS = 0; JS < 4; JS++) {
        uint32_t a[4];
        a[0] = pack_h2(sacc[2 * JS][0],     sacc[2 * JS][1]);
        a[1] = pack_h2(sacc[2 * JS][2],     sacc[2 * JS][3]);
        a[2] = pack_h2(sacc[2 * JS + 1][0], sacc[2 * JS + 1][1]);
        a[3] = pack_h2(sacc[2 * JS + 1][2], sacc[2 * JS + 1][3]);
#pragma unroll
        for (int nd = 0; nd < 8; nd++) {
            const int c = nd * 8 + gid;
            const uint32_t b0 = sV[(JS * 8 + tig) * KVPITCH + c];
            const uint32_t b1 = sV[(JS * 8 + 4 + tig) * KVPITCH + c];
            mma_f16(oacc[nd], a, b0, b1);
        }
    }

    // ---- epilogue: half2 stores into g_att ----
    const int grow = b * 64 + r0;
#pragma unroll
    for (int nd = 0; nd < 8; nd++) {
        const int col = h * 64 + nd * 8 + tig * 2;
        *(uint32_t*)(g_att + (size_t)grow * 512 + col) =
            pack_h2(oacc[nd][0], oacc[nd][1]);
        *(uint32_t*)(g_att + (size_t)(grow + 8) * 512 + col) =
            pack_h2(oacc[nd][2], oacc[nd][3]);
    }
}

__global__ void tail_zero(float* __restrict__ out, long long start, long long total)
{
    long long i = start + (long long)blockIdx.x * blockDim.x + threadIdx.x;
    if (i < total) out[i] = 0.0f;
}

// ---------------------------------------------------------------------------
extern "C" void kernel_launch(void* const* d_in, const int* in_sizes, int n_in,
                              void* d_out, int out_size)
{
    const float* x    = (const float*)d_in[0];
    const float* mask = (const float*)d_in[1];
    const float* Wq   = (const float*)d_in[2];
    const float* bq   = (const float*)d_in[3];
    const float* Wk   = (const float*)d_in[4];
    const float* bk   = (const float*)d_in[5];
    const float* Wv   = (const float*)d_in[6];
    const float* bv   = (const float*)d_in[7];
    const float* Wo   = (const float*)d_in[8];
    const float* bo   = (const float*)d_in[9];
    float* out = (float*)d_out;

    // 0) Tail first (ccd_loss scalar / padding)
    long long tail = (long long)out_size - OUT_ELEMS;
    if (tail > 0) {
        int blocks = (int)((tail + 255) / 256);
        tail_zero<<<blocks, 256>>>(out, OUT_ELEMS, (long long)out_size);
    }

    // 1) Fused QKV projections (grid.x = 12 -> {q,k,v} x 4 n-tiles of 128)
    gemm_f16<<<dim3(12, 1024), 256>>>(x, nullptr, Wq, Wk, Wv, bq, bk, bv, 0);

    // 2) Channel-masked attention (tensor-core)
    attn_mma<<<dim3(HEADS, BATCH), 128>>>(mask);

    // 3) Output projection (grid.x = 4)
    gemm_f16<<<dim3(4, 1024), 256>>>(nullptr, out, Wo, Wo, Wo, bo, bo, bo, 1);
}